// round 16
// baseline (speedup 1.0000x reference)
#include <cuda_runtime.h>
#include <cuda_bf16.h>
#include <math.h>

#define B     64
#define N     196
#define TT    32
#define STEPS 31
#define VOCAB 32000
#define EMB   256
#define HDIM  512
#define VDIM  256
#define ATTD  256
#define G4    2048

// ---------------- scratch (device globals; no allocation) ----------------
__device__ float g_Uv[B * N * ATTD];
__device__ float g_h[B * HDIM];
__device__ float g_c[2][B * HDIM];        // parity double-buffer
__device__ float g_ctx[B * VDIM];
__device__ float g_hW[B * ATTD];          // prologue only
__device__ float g_gpart[8 * B * G4];     // split-K partials for gates (8 chunks)
__device__ float g_pp[4 * B * 512];       // producer GEMV partials (4 k-slices)
__device__ __align__(16) __nv_bfloat16 g_hpb[128 * EMB];        // rows 0-63 hi, 64-127 lo
__device__ __align__(16) __nv_bfloat16 g_eh[(size_t)VOCAB * EMB];
__device__ __align__(16) __nv_bfloat16 g_el[(size_t)VOCAB * EMB];
__device__ unsigned g_flag_pp;            // producer arrivals   (256 / step)
__device__ unsigned g_flag_hp;            // reducer hp arrivals (64 / step)
__device__ unsigned g_flag_ctx;           // reducer ctx arrivals(64 / step)

__device__ __forceinline__ float sigmoidf_(float x) { return 1.f / (1.f + expf(-x)); }
__device__ __forceinline__ float tanh_fast(float x) {
    float y;
    asm("tanh.approx.f32 %0, %1;" : "=f"(y) : "f"(x));
    return y;
}

// ---------------- packed f32x2 FMA helpers (SIMT GEMMs) ----------------
typedef unsigned long long ull;
struct Acc44 { ull a[4][2]; };
__device__ __forceinline__ ull fma2(ull a, ull b, ull c) {
    ull d; asm("fma.rn.f32x2 %0, %1, %2, %3;" : "=l"(d) : "l"(a), "l"(b), "l"(c));
    return d;
}
__device__ __forceinline__ ull pack2(float x) {
    ull d; unsigned int xi = __float_as_uint(x);
    asm("mov.b64 %0, {%1, %1};" : "=l"(d) : "r"(xi));
    return d;
}
__device__ __forceinline__ void acc_zero(Acc44& A) {
    #pragma unroll
    for (int i = 0; i < 4; i++) { A.a[i][0] = 0ull; A.a[i][1] = 0ull; }
}
__device__ __forceinline__ void mma44(Acc44& A, float4 xf, ulonglong2 wf) {
    ull h;
    h = pack2(xf.x); A.a[0][0] = fma2(h, wf.x, A.a[0][0]); A.a[0][1] = fma2(h, wf.y, A.a[0][1]);
    h = pack2(xf.y); A.a[1][0] = fma2(h, wf.x, A.a[1][0]); A.a[1][1] = fma2(h, wf.y, A.a[1][1]);
    h = pack2(xf.z); A.a[2][0] = fma2(h, wf.x, A.a[2][0]); A.a[2][1] = fma2(h, wf.y, A.a[2][1]);
    h = pack2(xf.w); A.a[3][0] = fma2(h, wf.x, A.a[3][0]); A.a[3][1] = fma2(h, wf.y, A.a[3][1]);
}
__device__ __forceinline__ float4 unpack44(const Acc44& A, int i) {
    unsigned int l0, h0, l1, h1;
    asm("mov.b64 {%0,%1}, %2;" : "=r"(l0), "=r"(h0) : "l"(A.a[i][0]));
    asm("mov.b64 {%0,%1}, %2;" : "=r"(l1), "=r"(h1) : "l"(A.a[i][1]));
    return make_float4(__uint_as_float(l0), __uint_as_float(h0),
                       __uint_as_float(l1), __uint_as_float(h1));
}

__device__ __forceinline__ unsigned smem_u32(const void* p) {
    unsigned a;
    asm("{ .reg .u64 t; cvta.to.shared.u64 t, %1; cvt.u32.u64 %0, t; }" : "=r"(a) : "l"(p));
    return a;
}

// acquire-spin on a monotonic flag (tid 0 spins, block syncs after)
__device__ __forceinline__ void wait_flag(unsigned* f, unsigned target) {
    if (threadIdx.x == 0) {
        unsigned v;
        for (;;) {
            asm volatile("ld.acquire.gpu.u32 %0, [%1];" : "=r"(v) : "l"(f) : "memory");
            if (v >= target) break;
            __nanosleep(64);
        }
    }
    __syncthreads();
}

// ---------------- init: feat_mean -> h0, c0 ----------------
__global__ void k_init_hc(const float* __restrict__ V,
                          const float* __restrict__ Wh, const float* __restrict__ bh,
                          const float* __restrict__ Wc, const float* __restrict__ bc) {
    int b = blockIdx.x, tid = threadIdx.x;
    __shared__ float fm[VDIM];
    if (tid < VDIM) {
        const float* vp = V + (size_t)b * N * VDIM + tid;
        float s = 0.f;
        for (int n = 0; n < N; n++) s += vp[(size_t)n * VDIM];
        fm[tid] = s * (1.f / (float)N);
    }
    __syncthreads();
    int j = tid;
    float ah = bh[j], ac = bc[j];
    #pragma unroll 4
    for (int v = 0; v < VDIM; v++) {
        float f = fm[v];
        ah += f * Wh[(size_t)v * HDIM + j];
        ac += f * Wc[(size_t)v * HDIM + j];
    }
    g_h[b * HDIM + j] = tanhf(ah);
    g_c[0][b * HDIM + j] = tanhf(ac);
}

// reset flags (start of every capture/replay)
__global__ void k_reset() { g_flag_pp = 0; g_flag_hp = 0; g_flag_ctx = 0; }

// ---------------- hW(h0) for step 0 ----------------
__global__ void k_hw0(const float* __restrict__ Watt) {
    int b = blockIdx.x, tid = threadIdx.x;
    __shared__ float hs[HDIM];
    __shared__ float red[1024];
    if (tid < 512) hs[tid] = g_h[b * HDIM + tid];
    __syncthreads();
    int jl = tid & 255, kh = tid >> 8;
    const float* W = Watt + (size_t)(kh * 128) * ATTD + jl;
    const float* hp = hs + kh * 128;
    float a0 = 0.f, a1 = 0.f, a2 = 0.f, a3 = 0.f;
    #pragma unroll 8
    for (int k = 0; k < 128; k += 4) {
        a0 += hp[k]     * W[(size_t)k * ATTD];
        a1 += hp[k + 1] * W[(size_t)(k + 1) * ATTD];
        a2 += hp[k + 2] * W[(size_t)(k + 2) * ATTD];
        a3 += hp[k + 3] * W[(size_t)(k + 3) * ATTD];
    }
    red[tid] = (a0 + a1) + (a2 + a3);
    __syncthreads();
    if (tid < 256)
        g_hW[b * ATTD + jl] = (red[jl] + red[jl + 256]) + (red[jl + 512] + red[jl + 768]);
}

// ---------------- Uv = V @ U_att (once) ----------------
#define UV_ROWS 16
__global__ void k_uv(const float* __restrict__ V, const float* __restrict__ U) {
    __shared__ float Vs[UV_ROWS * VDIM];
    int r0 = blockIdx.x * UV_ROWS;
    int tid = threadIdx.x;
    for (int i = tid; i < UV_ROWS * VDIM; i += 256)
        Vs[i] = V[(size_t)r0 * VDIM + i];
    __syncthreads();
    float acc[UV_ROWS];
    #pragma unroll
    for (int i = 0; i < UV_ROWS; i++) acc[i] = 0.f;
    int a = tid;
    #pragma unroll 4
    for (int v = 0; v < VDIM; v++) {
        float u = U[(size_t)v * ATTD + a];
        #pragma unroll
        for (int i = 0; i < UV_ROWS; i++) acc[i] += Vs[i * VDIM + v] * u;
    }
    #pragma unroll
    for (int i = 0; i < UV_ROWS; i++)
        g_Uv[(size_t)(r0 + i) * ATTD + a] = acc[i];
}

// ---------------- embed -> bf16 hi/lo (once) ----------------
__global__ void k_esplit(const float* __restrict__ e) {
    size_t i = ((size_t)blockIdx.x * 256 + threadIdx.x) * 2;
    float2 v = *(const float2*)(e + i);
    __nv_bfloat16 h0 = __float2bfloat16(v.x);
    __nv_bfloat16 h1 = __float2bfloat16(v.y);
    __nv_bfloat16 l0 = __float2bfloat16(v.x - __bfloat162float(h0));
    __nv_bfloat16 l1 = __float2bfloat16(v.y - __bfloat162float(h1));
    *(__nv_bfloat162*)(g_eh + i) = __nv_bfloat162(h0, h1);
    *(__nv_bfloat162*)(g_el + i) = __nv_bfloat162(l0, l1);
}

// ---------------- prologue attention (ctx for step 0, reads g_hW) ----------------
__global__ void k_att0(const float* __restrict__ vatt, const float* __restrict__ V) {
    int b = blockIdx.x, tid = threadIdx.x;
    __shared__ float hWs[ATTD];
    __shared__ float vs[ATTD];
    __shared__ float es[256];
    __shared__ float red[256];
    __shared__ float ctxp[512];
    if (tid < 256) {
        hWs[tid] = g_hW[b * ATTD + tid];
        vs[tid] = vatt[tid];
    }
    __syncthreads();
    int warp = tid >> 5, lane = tid & 31;
    for (int n = warp; n < N; n += 16) {
        const float* uv = g_Uv + (size_t)(b * N + n) * ATTD;
        float p = 0.f;
        #pragma unroll
        for (int j = 0; j < 8; j++) {
            int a = lane + 32 * j;
            p += tanh_fast(hWs[a] + uv[a]) * vs[a];
        }
        #pragma unroll
        for (int off = 16; off > 0; off >>= 1)
            p += __shfl_down_sync(0xffffffffu, p, off);
        if (lane == 0) es[n] = p;
    }
    __syncthreads();
    float v = (tid < N) ? es[tid] : -INFINITY;
    if (tid < 256) red[tid] = v;
    __syncthreads();
    for (int s = 128; s > 0; s >>= 1) {
        if (tid < s) red[tid] = fmaxf(red[tid], red[tid + s]);
        __syncthreads();
    }
    float mx = red[0];
    __syncthreads();
    float ex = (tid < N) ? expf(v - mx) : 0.f;
    if (tid < 256) red[tid] = ex;
    __syncthreads();
    for (int s = 128; s > 0; s >>= 1) {
        if (tid < s) red[tid] += red[tid + s];
        __syncthreads();
    }
    float inv = 1.f / red[0];
    __syncthreads();
    if (tid < N) es[tid] = ex * inv;
    __syncthreads();
    int half = tid >> 8, vd = tid & 255;
    const float* vp = V + (size_t)b * N * VDIM + (size_t)half * 98 * VDIM + vd;
    float acc = 0.f;
    #pragma unroll 7
    for (int n = 0; n < 98; n++) acc += es[half * 98 + n] * vp[(size_t)n * VDIM];
    ctxp[tid] = acc;
    __syncthreads();
    if (tid < 256) g_ctx[b * VDIM + tid] = ctxp[tid] + ctxp[tid + 256];
}

// ================= gates body (split-K x8), 256 threads =================
__device__ __forceinline__ void gates_body(char* smc, const float* __restrict__ embed,
                                           const int* __restrict__ y,
                                           const float* __restrict__ Wih,
                                           const float* __restrict__ Whh,
                                           int t, int j0, int kc, unsigned wait_target) {
    float* Xs = (float*)smc;                 // [128 kk][68 pad]
    float* Ws = (float*)smc + 128 * 68;      // [128 kk][64 jj]
    int tid = threadIdx.x;

    const float* W = (kc < 4) ? (Wih + (size_t)(kc * 128) * G4)
                              : (Whh + (size_t)((kc - 4) * 128) * G4);
    for (int idx = tid; idx < 128 * 64; idx += 256) {
        int kk = idx >> 6, jj = idx & 63;
        Ws[idx] = W[(size_t)kk * G4 + j0 + jj];
    }
    if (wait_target) wait_flag(&g_flag_ctx, wait_target);

    for (int idx = tid; idx < B * 128; idx += 256) {
        int kk = idx & 127, bb = idx >> 7;
        int gk = kc * 128 + kk;
        float x;
        if (gk < 256)      x = embed[(size_t)y[bb * TT + t] * EMB + gk];
        else if (gk < 512) x = g_ctx[bb * VDIM + (gk - 256)];
        else               x = g_h[bb * HDIM + (gk - 512)];
        Xs[kk * 68 + bb] = x;
    }
    __syncthreads();

    int tx = tid & 15, ty = tid >> 4;
    Acc44 A; acc_zero(A);
    #pragma unroll 4
    for (int kk = 0; kk < 128; kk++) {
        float4 xf = *(const float4*)&Xs[kk * 68 + ty * 4];
        ulonglong2 wf = *(const ulonglong2*)&Ws[kk * 64 + tx * 4];
        mma44(A, xf, wf);
    }
    float* gp = g_gpart + (size_t)kc * B * G4;
    #pragma unroll
    for (int i = 0; i < 4; i++) {
        int bb = ty * 4 + i;
        *(float4*)&gp[(size_t)bb * G4 + j0 + tx * 4] = unpack44(A, i);
    }
}

// prologue-only standalone gates (no wait)
__global__ void k_gates(const float* __restrict__ embed, const int* __restrict__ y,
                        const float* __restrict__ Wih, const float* __restrict__ Whh, int t) {
    extern __shared__ char smc[];
    gates_body(smc, embed, y, Wih, Whh, t, (blockIdx.x & 31) * 64, blockIdx.x >> 5, 0u);
}

// ================= producer: LSTM + 128-k GEMV partial for all 512 outputs =================
__device__ __forceinline__ void producer_body(char* smc,
                                              const float* __restrict__ bih,
                                              const float* __restrict__ bhh,
                                              const float* __restrict__ Wproj,
                                              const float* __restrict__ Watt,
                                              int parity, int b, int kh) {
    float* hs = (float*)smc;         // [512]
    int tid = threadIdx.x;

    // LSTM pointwise: 2 j's per thread (redundant across kh; kh=0 commits)
    #pragma unroll
    for (int jj = 0; jj < 2; jj++) {
        int j = tid + jj * 256;
        float gi = bih[j]        + bhh[j];
        float gf = bih[512 + j]  + bhh[512 + j];
        float gg = bih[1024 + j] + bhh[1024 + j];
        float go = bih[1536 + j] + bhh[1536 + j];
        #pragma unroll
        for (int kc = 0; kc < 8; kc++) {
            const float* gp = g_gpart + (size_t)kc * B * G4 + (size_t)b * G4;
            gi += gp[j]; gf += gp[512 + j]; gg += gp[1024 + j]; go += gp[1536 + j];
        }
        float c = sigmoidf_(gf) * g_c[parity][b * HDIM + j] + sigmoidf_(gi) * tanhf(gg);
        float h = sigmoidf_(go) * tanhf(c);
        if (kh == 0) {
            g_c[parity ^ 1][b * HDIM + j] = c;
            g_h[b * HDIM + j] = h;
        }
        hs[j] = h;
    }
    __syncthreads();

    // GEMV partial over k in [kh*128, kh*128+128); outputs: hp col tid, hW col tid
    const float* hb = hs + kh * 128;
    const float* W1 = Wproj + (size_t)(kh * 128) * 256 + tid;
    const float* W2 = Watt  + (size_t)(kh * 128) * 256 + tid;
    float a[16];
    #pragma unroll
    for (int i = 0; i < 16; i++) a[i] = 0.f;
    #pragma unroll 2
    for (int k = 0; k < 128; k += 8) {
        #pragma unroll
        for (int i = 0; i < 8; i++) {
            float hv = hb[k + i];
            a[i]     += hv * W1[(size_t)(k + i) * 256];
            a[8 + i] += hv * W2[(size_t)(k + i) * 256];
        }
    }
    float p1 = ((a[0] + a[1]) + (a[2] + a[3])) + ((a[4] + a[5]) + (a[6] + a[7]));
    float p2 = ((a[8] + a[9]) + (a[10] + a[11])) + ((a[12] + a[13]) + (a[14] + a[15]));
    float* pp = g_pp + ((size_t)kh * B + b) * 512;
    pp[tid] = p1;
    pp[256 + tid] = p2;
    __threadfence();
    __syncthreads();
    if (tid == 0) atomicAdd(&g_flag_pp, 1u);
}

// ================= reducer: sum partials -> hpb (flag) + attention -> ctx (flag) =================
__device__ __forceinline__ void reducer_body(char* smc,
                                             const float* __restrict__ vatt,
                                             const float* __restrict__ V,
                                             int b, unsigned pp_target) {
    float* hWs = (float*)smc;        // [256]
    float* vs  = hWs + 256;          // [256]
    float* es  = vs + 256;           // [256]
    float* red = es + 256;           // [256]
    int tid = threadIdx.x;

    wait_flag(&g_flag_pp, pp_target);

    float s1 = 0.f, s2 = 0.f;
    #pragma unroll
    for (int kh = 0; kh < 4; kh++) {
        const float* pp = g_pp + ((size_t)kh * B + b) * 512;
        s1 += pp[tid];
        s2 += pp[256 + tid];
    }
    // hp -> bf16 hi/lo
    __nv_bfloat16 hi = __float2bfloat16(s1);
    __nv_bfloat16 lo = __float2bfloat16(s1 - __bfloat162float(hi));
    g_hpb[b * EMB + tid] = hi;
    g_hpb[(64 + b) * EMB + tid] = lo;
    __threadfence();
    __syncthreads();
    if (tid == 0) atomicAdd(&g_flag_hp, 1u);

    // attention
    hWs[tid] = s2;
    vs[tid] = vatt[tid];
    __syncthreads();
    int warp = tid >> 5, lane = tid & 31;
    for (int n = warp; n < N; n += 8) {
        const float* uv = g_Uv + (size_t)(b * N + n) * ATTD;
        float p = 0.f;
        #pragma unroll
        for (int q = 0; q < 8; q++) {
            int aidx = lane + 32 * q;
            p += tanh_fast(hWs[aidx] + uv[aidx]) * vs[aidx];
        }
        #pragma unroll
        for (int off = 16; off > 0; off >>= 1)
            p += __shfl_down_sync(0xffffffffu, p, off);
        if (lane == 0) es[n] = p;
    }
    __syncthreads();
    float v = (tid < N) ? es[tid] : -INFINITY;
    red[tid] = v;
    __syncthreads();
    for (int st = 128; st > 0; st >>= 1) {
        if (tid < st) red[tid] = fmaxf(red[tid], red[tid + st]);
        __syncthreads();
    }
    float mx = red[0];
    __syncthreads();
    float ex = (tid < N) ? expf(v - mx) : 0.f;
    red[tid] = ex;
    __syncthreads();
    for (int st = 128; st > 0; st >>= 1) {
        if (tid < st) red[tid] += red[tid + st];
        __syncthreads();
    }
    float inv = 1.f / red[0];
    __syncthreads();
    if (tid < N) es[tid] = ex * inv;
    __syncthreads();
    // ctx: 196-dot per thread, 16 accumulators
    const float* vp = V + (size_t)b * N * VDIM + tid;
    float ca[16];
    #pragma unroll
    for (int i = 0; i < 16; i++) ca[i] = 0.f;
    int n = 0;
    #pragma unroll 2
    for (; n + 16 <= N; n += 16) {
        #pragma unroll
        for (int i = 0; i < 16; i++)
            ca[i] += es[n + i] * vp[(size_t)(n + i) * VDIM];
    }
    for (; n < N; n++) ca[0] += es[n] * vp[(size_t)n * VDIM];
    float s = 0.f;
    #pragma unroll
    for (int i = 0; i < 16; i++) s += ca[i];
    g_ctx[b * VDIM + tid] = s;
    __threadfence();
    __syncthreads();
    if (tid == 0) atomicAdd(&g_flag_ctx, 1u);
}

// ================= logits body (mma.sync bf16 hi/lo), 256 threads =================
#define SA  0
#define SBH 32768
#define SBL (SBH + 34816)
#define SM_LOG (SBL + 34816)   // 102400

__device__ __forceinline__ void logits_body(char* smc, float* __restrict__ out,
                                            int t, int v0, unsigned hp_target) {
    const unsigned sb = smem_u32(smc);
    int tid = threadIdx.x;
    int wid = tid >> 5, lane = tid & 31;
    int wr = wid & 3, wc = wid >> 2;
    bool hiwarp = (wr < 2);

    float d[16][4];
    #pragma unroll
    for (int f = 0; f < 16; f++) { d[f][0] = d[f][1] = d[f][2] = d[f][3] = 0.f; }

    int bmat = lane >> 3, brow = lane & 7;
    int bn_local = ((bmat >> 1) << 3) + brow;
    unsigned bkoff = (unsigned)((bmat & 1) << 3) * 2;

    #pragma unroll
    for (int kc = 0; kc < 2; kc++) {
        // B tiles first (independent of producers)
        for (int i = tid; i < 2048; i += 256) {
            int n = i >> 4, u = i & 15;
            size_t go = (size_t)(v0 + n) * 512 + kc * 256 + u * 16;
            *(uint4*)(smc + SBH + n * 272 + u * 16) = *(const uint4*)((const char*)g_eh + go);
            *(uint4*)(smc + SBL + n * 272 + u * 16) = *(const uint4*)((const char*)g_el + go);
        }
        if (kc == 0 && hp_target) wait_flag(&g_flag_hp, hp_target);
        for (int i = tid; i < 2048; i += 256) {
            int m = i >> 4, u = i & 15;
            *(uint4*)(smc + SA + m * 256 + ((u ^ (m & 7)) << 4)) =
                *(const uint4*)((const char*)g_hpb + (size_t)m * 512 + kc * 256 + u * 16);
        }
        __syncthreads();

        #pragma unroll
        for (int ks = 0; ks < 8; ks++) {
            unsigned a[2][4];
            #pragma unroll
            for (int mi = 0; mi < 2; mi++) {
                int m = wr * 32 + mi * 16 + ((lane >> 3) & 1) * 8 + (lane & 7);
                int u = ks * 2 + (lane >> 4);
                unsigned addr = sb + SA + m * 256 + ((u ^ (m & 7)) << 4);
                asm volatile(
                    "ldmatrix.sync.aligned.m8n8.x4.shared.b16 {%0,%1,%2,%3}, [%4];"
                    : "=r"(a[mi][0]), "=r"(a[mi][1]), "=r"(a[mi][2]), "=r"(a[mi][3])
                    : "r"(addr));
            }
            unsigned bko = (unsigned)(ks * 32) + bkoff;
            #pragma unroll
            for (int np = 0; np < 4; np++) {
                unsigned brow_addr = sb + SBH +
                    (unsigned)((wc * 64 + np * 16 + bn_local) * 272) + bko;
                unsigned bh[4];
                asm volatile(
                    "ldmatrix.sync.aligned.m8n8.x4.shared.b16 {%0,%1,%2,%3}, [%4];"
                    : "=r"(bh[0]), "=r"(bh[1]), "=r"(bh[2]), "=r"(bh[3])
                    : "r"(brow_addr));
                #pragma unroll
                for (int half = 0; half < 2; half++) {
                    int f0 = np * 2 + half;
                    #pragma unroll
                    for (int mi = 0; mi < 2; mi++) {
                        int f = mi * 8 + f0;
                        asm volatile(
                            "mma.sync.aligned.m16n8k16.row.col.f32.bf16.bf16.f32 "
                            "{%0,%1,%2,%3}, {%4,%5,%6,%7}, {%8,%9}, {%0,%1,%2,%3};"
                            : "+f"(d[f][0]), "+f"(d[f][1]), "+f"(d[f][2]), "+f"(d[f][3])
                            : "r"(a[mi][0]), "r"(a[mi][1]), "r"(a[mi][2]), "r"(a[mi][3]),
                              "r"(bh[half * 2]), "r"(bh[half * 2 + 1]));
                    }
                }
                if (hiwarp) {
                    unsigned blo_addr = brow_addr + (SBL - SBH);
                    unsigned bl[4];
                    asm volatile(
                        "ldmatrix.sync.aligned.m8n8.x4.shared.b16 {%0,%1,%2,%3}, [%4];"
                        : "=r"(bl[0]), "=r"(bl[1]), "=r"(bl[2]), "=r"(bl[3])
                        : "r"(blo_addr));
                    #pragma unroll
                    for (int half = 0; half < 2; half++) {
                        int f0 = np * 2 + half;
                        #pragma unroll
                        for (int mi = 0; mi < 2; mi++) {
                            int f = mi * 8 + f0;
                            asm volatile(
                                "mma.sync.aligned.m16n8k16.row.col.f32.bf16.bf16.f32 "
                                "{%0,%1,%2,%3}, {%4,%5,%6,%7}, {%8,%9}, {%0,%1,%2,%3};"
                                : "+f"(d[f][0]), "+f"(d[f][1]), "+f"(d[f][2]), "+f"(d[f][3])
                                : "r"(a[mi][0]), "r"(a[mi][1]), "r"(a[mi][2]), "r"(a[mi][3]),
                                  "r"(bl[half * 2]), "r"(bl[half * 2 + 1]));
                        }
                    }
                }
            }
        }
        __syncthreads();
    }

    float* epi = (float*)(smc + SA);
    if (wr >= 2) {
        #pragma unroll
        for (int mi = 0; mi < 2; mi++) {
            int r0 = (wr - 2) * 32 + mi * 16 + (lane >> 2);
            #pragma unroll
            for (int nf = 0; nf < 8; nf++) {
                int f = mi * 8 + nf;
                int col = wc * 64 + nf * 8 + (lane & 3) * 2;
                epi[r0 * 128 + col]           = d[f][0];
                epi[r0 * 128 + col + 1]       = d[f][1];
                epi[(r0 + 8) * 128 + col]     = d[f][2];
                epi[(r0 + 8) * 128 + col + 1] = d[f][3];
            }
        }
    }
    __syncthreads();
    if (wr < 2) {
        #pragma unroll
        for (int mi = 0; mi < 2; mi++) {
            int b0 = wr * 32 + mi * 16 + (lane >> 2);
            #pragma unroll
            for (int nf = 0; nf < 8; nf++) {
                int f = mi * 8 + nf;
                int col = wc * 64 + nf * 8 + (lane & 3) * 2;
                float2 r0v = make_float2(d[f][0] + epi[b0 * 128 + col],
                                         d[f][1] + epi[b0 * 128 + col + 1]);
                float2 r1v = make_float2(d[f][2] + epi[(b0 + 8) * 128 + col],
                                         d[f][3] + epi[(b0 + 8) * 128 + col + 1]);
                *(float2*)(out + ((size_t)b0 * STEPS + t) * VOCAB + v0 + col) = r0v;
                *(float2*)(out + ((size_t)(b0 + 8) * STEPS + t) * VOCAB + v0 + col) = r1v;
            }
        }
    }
}

// ================= mega step kernel =================
// 826 blocks: [0,256) producers, [256,320) reducers, [320,570) logits(t), [570,826) gates(t+1)
__global__ void __launch_bounds__(256, 2)
k_step(float* __restrict__ out, int t,
       const float* __restrict__ embed, const int* __restrict__ y,
       const float* __restrict__ Wih, const float* __restrict__ Whh,
       const float* __restrict__ bih, const float* __restrict__ bhh,
       const float* __restrict__ Wproj, const float* __restrict__ Watt,
       const float* __restrict__ vatt, const float* __restrict__ V, int parity) {
    extern __shared__ char smc[];
    int bid = blockIdx.x;
    if (bid < 256) {
        producer_body(smc, bih, bhh, Wproj, Watt, parity, bid >> 2, bid & 3);
    } else if (bid < 320) {
        reducer_body(smc, vatt, V, bid - 256, 256u * (unsigned)(t + 1));
    } else if (bid < 570) {
        logits_body(smc, out, t, (bid - 320) * 128, 64u * (unsigned)(t + 1));
    } else {
        int idx = bid - 570;
        gates_body(smc, embed, y, Wih, Whh, t + 1, (idx & 31) * 64, idx >> 5,
                   64u * (unsigned)(t + 1));
    }
}

// ---------------- launch ----------------
extern "C" void kernel_launch(void* const* d_in, const int* in_sizes, int n_in,
                              void* d_out, int out_size) {
    const float* V      = (const float*)d_in[0];
    const int*   y      = (const int*)  d_in[1];
    const float* embed  = (const float*)d_in[2];
    const float* W_att  = (const float*)d_in[3];
    const float* U_att  = (const float*)d_in[4];
    const float* v_att  = (const float*)d_in[5];
    const float* W_ih   = (const float*)d_in[6];
    const float* W_hh   = (const float*)d_in[7];
    const float* b_ih   = (const float*)d_in[8];
    const float* b_hh   = (const float*)d_in[9];
    const float* W_inith = (const float*)d_in[10];
    const float* b_inith = (const float*)d_in[11];
    const float* W_initc = (const float*)d_in[12];
    const float* b_initc = (const float*)d_in[13];
    const float* W_proj  = (const float*)d_in[14];
    float* out = (float*)d_out;

    const int SMEM_GATES = (128 * 68 + 128 * 64) * sizeof(float);  // 67584
    cudaFuncSetAttribute(k_gates, cudaFuncAttributeMaxDynamicSharedMemorySize, SMEM_GATES);
    cudaFuncSetAttribute(k_step,  cudaFuncAttributeMaxDynamicSharedMemorySize, SM_LOG);

    k_reset<<<1, 1>>>();
    k_init_hc<<<B, 512>>>(V, W_inith, b_inith, W_initc, b_initc);
    k_uv<<<(B * N) / UV_ROWS, 256>>>(V, U_att);
    k_esplit<<<(VOCAB * EMB) / 512, 256>>>(embed);
    k_hw0<<<B, 1024>>>(W_att);                                   // hW(h0)
    k_att0<<<B, 512>>>(v_att, V);                                // ctx(0)
    k_gates<<<256, 256, SMEM_GATES>>>(embed, y, W_ih, W_hh, 0);  // gates(0)

    for (int t = 0; t < STEPS; t++) {
        k_step<<<826, 256, SM_LOG>>>(out, t, embed, y, W_ih, W_hh,
                                     b_ih, b_hh, W_proj, W_att, v_att, V, t & 1);
    }
}